// round 12
// baseline (speedup 1.0000x reference)
#include <cuda_runtime.h>
#include <cuda_bf16.h>
#include <math.h>
#include <stdint.h>

// Problem constants (fixed by reference)
#define BB      2
#define TT      8192
#define EE      256
#define CSZ     128
#define NN      64        // TT / CSZ
#define NSEL    7         // K - 1
#define LEXT    1024      // K * CS
#define EPSF    1e-6f

// common staged-tile strides
#define LDBE    40        // bf16 row stride of [rows][k32] tiles (80 B)

// score kernel smem (CTA tile 128 x 256, k-chunk 32)
#define S_AH    0
#define S_AL    10240
#define S_BH    20480                 // 256 rows x 80B
#define S_BL    40960
#define S_STG   61440
#define S_SMAX  (2 * S_STG)           // float[4][128]
#define S_PART  (S_SMAX + 2048)       // float[8]
#define SCORE_SMEM (S_PART + 64)

// out kernel smem (CTA tile 128 x 256, k-chunk 32)
#define O_AH    0
#define O_AL    10240
#define O_BH    20480                 // B: [32 l][264 e-stride] bf16 = 16896 B
#define O_BL    (20480 + 16896)
#define O_STG   (20480 + 2 * 16896)  // 54272
#define OUT_SMEM (2 * O_STG + 128)
#define OLDE2   528                   // B row stride in bytes (264 bf16)

// ---------------------------------------------------------------------------
// Scratch (static device globals — no allocation)
// ---------------------------------------------------------------------------
__device__ __nv_bfloat16 g_hi[(size_t)BB * TT * EE];   // bf16(cn), 8 MB
__device__ __nv_bfloat16 g_lo[(size_t)BB * TT * EE];   // bf16(cn - hi), 8 MB
__device__ __nv_bfloat16 g_xhi[(size_t)BB * TT * EE];  // bf16(x), 8 MB
__device__ __nv_bfloat16 g_xlo[(size_t)BB * TT * EE];  // bf16(x - xhi), 8 MB
__device__ float g_scores[BB * NN * NN];
__device__ int   g_selidx[BB * NN * NSEL];
__device__ float g_selw[BB * NN * NSEL];

// ---------------------------------------------------------------------------
// Base-PTX helpers (no 'a'-target instructions!)
// ---------------------------------------------------------------------------
__device__ __forceinline__ uint32_t smem_u32(const void* p) {
    uint32_t a;
    asm("{ .reg .u64 t; cvta.to.shared.u64 t, %1; cvt.u32.u64 %0, t; }"
        : "=r"(a) : "l"(p));
    return a;
}
__device__ __forceinline__ void cp16(uint32_t dst, const void* src) {
    asm volatile("cp.async.cg.shared.global [%0], [%1], 16;" :: "r"(dst), "l"(src));
}
__device__ __forceinline__ void cp_commit() {
    asm volatile("cp.async.commit_group;" ::: "memory");
}
template<int N> __device__ __forceinline__ void cp_wait() {
    asm volatile("cp.async.wait_group %0;" :: "n"(N) : "memory");
}
__device__ __forceinline__ void ldmx4(uint32_t* r, uint32_t addr) {
    asm volatile("ldmatrix.sync.aligned.m8n8.x4.shared.b16 {%0,%1,%2,%3}, [%4];"
                 : "=r"(r[0]), "=r"(r[1]), "=r"(r[2]), "=r"(r[3]) : "r"(addr));
}
__device__ __forceinline__ void ldmx4t(uint32_t* r, uint32_t addr) {
    asm volatile("ldmatrix.sync.aligned.m8n8.x4.trans.shared.b16 {%0,%1,%2,%3}, [%4];"
                 : "=r"(r[0]), "=r"(r[1]), "=r"(r[2]), "=r"(r[3]) : "r"(addr));
}
__device__ __forceinline__ void mma16816(float* c, const uint32_t* a, const uint32_t* b) {
    asm volatile("mma.sync.aligned.m16n8k16.row.col.f32.bf16.bf16.f32 "
                 "{%0,%1,%2,%3}, {%4,%5,%6,%7}, {%8,%9}, {%0,%1,%2,%3};"
                 : "+f"(c[0]), "+f"(c[1]), "+f"(c[2]), "+f"(c[3])
                 : "r"(a[0]), "r"(a[1]), "r"(a[2]), "r"(a[3]),
                   "r"(b[0]), "r"(b[1]));
}
__device__ __forceinline__ uint32_t pack2(unsigned short a, unsigned short b) {
    return (uint32_t)a | ((uint32_t)b << 16);
}
__device__ __forceinline__ void split_bf16(float f, unsigned short& h, unsigned short& l) {
    __nv_bfloat16 hb = __float2bfloat16(f);
    __nv_bfloat16 lb = __float2bfloat16(f - __bfloat162float(hb));
    h = *reinterpret_cast<unsigned short*>(&hb);
    l = *reinterpret_cast<unsigned short*>(&lb);
}

// ---------------------------------------------------------------------------
// Kernel A: row-normalize + hi/lo bf16 split of cn AND raw x.  One warp/row.
// ---------------------------------------------------------------------------
__global__ __launch_bounds__(256) void normalize_kernel(const float* __restrict__ x) {
    int row  = blockIdx.x * 8 + (threadIdx.x >> 5);
    int lane = threadIdx.x & 31;
    const float4* xr = (const float4*)(x + (size_t)row * EE);
    float4 v0 = xr[lane];
    float4 v1 = xr[lane + 32];
    float ss = v0.x*v0.x + v0.y*v0.y + v0.z*v0.z + v0.w*v0.w
             + v1.x*v1.x + v1.y*v1.y + v1.z*v1.z + v1.w*v1.w;
    #pragma unroll
    for (int off = 16; off; off >>= 1)
        ss += __shfl_xor_sync(0xffffffffu, ss, off);
    float inv = 1.0f / (sqrtf(ss) + EPSF);

    #pragma unroll
    for (int g = 0; g < 2; g++) {
        float4 v = g ? v1 : v0;
        float fr[4] = {v.x, v.y, v.z, v.w};
        unsigned short h[4], l[4], xh[4], xl[4];
        #pragma unroll
        for (int q = 0; q < 4; q++) {
            split_bf16(fr[q] * inv, h[q], l[q]);
            split_bf16(fr[q], xh[q], xl[q]);
        }
        size_t e = (size_t)row * EE + ((size_t)lane + (g ? 32 : 0)) * 4;
        *(uint2*)(g_hi  + e) = make_uint2(pack2(h[0],h[1]),  pack2(h[2],h[3]));
        *(uint2*)(g_lo  + e) = make_uint2(pack2(l[0],l[1]),  pack2(l[2],l[3]));
        *(uint2*)(g_xhi + e) = make_uint2(pack2(xh[0],xh[1]), pack2(xh[2],xh[3]));
        *(uint2*)(g_xlo + e) = make_uint2(pack2(xl[0],xl[1]), pack2(xl[2],xl[3]));
    }
}

// ---------------------------------------------------------------------------
// Kernel B: pair scores via mma.sync bf16 hi/lo (3-product fp32 emulation).
// CTA = (pair-block t, b): row chunk i vs TWO column chunks (j0, j1).
// C = cn_i @ [cn_j0 | cn_j1]^T (128 x 256 x 256).
// 8 warps in 2(M) x 4(N); each warp computes 64x64 of C.
// ---------------------------------------------------------------------------
__global__ __launch_bounds__(256) void score_kernel() {
    int t = blockIdx.x, b = blockIdx.y;
    // decode t -> (i, jb): blocks before row i: f(2m+1)=m(m+1), f(2m+2)=(m+1)^2
    int u = (int)floorf(sqrtf((float)t));
    while ((u + 1) * (u + 1) <= t) u++;
    while (u * u > t) u--;
    int i, jb;
    if (t >= u * u + u) { i = 2 * u + 1; jb = t - u * u - u; }
    else                { i = 2 * u;     jb = t - u * u; }
    int j0 = 2 * jb;
    int j1 = j0 + 1;
    int have1 = (j1 < i);
    int j1c = have1 ? j1 : j0;

    extern __shared__ char sm[];
    uint32_t smb = smem_u32(sm);
    int tid = threadIdx.x, lane = tid & 31, wid = tid >> 5;
    int wm = wid & 1, wn = wid >> 1;

    const __nv_bfloat16* Ah  = g_hi + ((size_t)b * TT + (size_t)i   * CSZ) * EE;
    const __nv_bfloat16* Al  = g_lo + ((size_t)b * TT + (size_t)i   * CSZ) * EE;
    const __nv_bfloat16* Bh0 = g_hi + ((size_t)b * TT + (size_t)j0  * CSZ) * EE;
    const __nv_bfloat16* Bl0 = g_lo + ((size_t)b * TT + (size_t)j0  * CSZ) * EE;
    const __nv_bfloat16* Bh1 = g_hi + ((size_t)b * TT + (size_t)j1c * CSZ) * EE;
    const __nv_bfloat16* Bl1 = g_lo + ((size_t)b * TT + (size_t)j1c * CSZ) * EE;

    float acc[4][8][4];
    #pragma unroll
    for (int mf = 0; mf < 4; mf++)
        #pragma unroll
        for (int nf = 0; nf < 8; nf++)
            #pragma unroll
            for (int q = 0; q < 4; q++) acc[mf][nf][q] = 0.0f;

    int g8  = lane & 7, sel = lane >> 3;
    int a_row = g8 + ((sel & 1) ? 8 : 0);
    int a_col = (sel & 2) ? 8 : 0;
    int b_row = g8 + ((sel >= 2) ? 8 : 0);
    int b_col = (sel & 1) ? 8 : 0;

    auto issue_stage = [&](int stage, int kt) {
        uint32_t sbase = smb + stage * S_STG;
        int k0 = kt * 32;
        // A: 2 tiles x 128 rows x 4 segs = 1024 chunks
        #pragma unroll
        for (int tt = 0; tt < 4; tt++) {
            int c = tid + tt * 256;
            int tile = c >> 9;
            int within = c & 511;
            int row = within >> 2, seg = within & 3;
            const __nv_bfloat16* src = (tile ? Al : Ah) + (size_t)row * EE + k0 + seg * 8;
            cp16(sbase + (tile ? S_AL : S_AH) + row * (LDBE * 2) + seg * 16, src);
        }
        // B: 2 tiles x 256 rows x 4 segs = 2048 chunks
        #pragma unroll
        for (int tt = 0; tt < 8; tt++) {
            int c = tid + tt * 256;
            int tile = c >> 10;
            int within = c & 1023;
            int row = within >> 2, seg = within & 3;    // row 0..255
            const __nv_bfloat16* base = (row < 128)
                ? (tile ? Bl0 : Bh0) : (tile ? Bl1 : Bh1);
            int rr = row & 127;
            cp16(sbase + (tile ? S_BL : S_BH) + row * (LDBE * 2) + seg * 16,
                 base + (size_t)rr * EE + k0 + seg * 8);
        }
    };

    issue_stage(0, 0);
    cp_commit();

    for (int kt = 0; kt < 8; kt++) {
        int buf = kt & 1;
        if (kt < 7) {
            issue_stage(buf ^ 1, kt + 1);
            cp_commit();
            cp_wait<1>();
        } else {
            cp_wait<0>();
        }
        __syncthreads();

        uint32_t sAh = smb + buf * S_STG + S_AH;
        uint32_t sAl = smb + buf * S_STG + S_AL;
        uint32_t sBh = smb + buf * S_STG + S_BH;
        uint32_t sBl = smb + buf * S_STG + S_BL;

        #pragma unroll
        for (int kk = 0; kk < 32; kk += 16) {
            uint32_t bH[8][2], bL[8][2];
            #pragma unroll
            for (int p = 0; p < 4; p++) {
                uint32_t off = (uint32_t)((wn * 64 + p * 16 + b_row) * (LDBE * 2)
                                          + (kk + b_col) * 2);
                uint32_t r[4];
                ldmx4(r, sBh + off);
                bH[2*p][0] = r[0]; bH[2*p][1] = r[1];
                bH[2*p+1][0] = r[2]; bH[2*p+1][1] = r[3];
                ldmx4(r, sBl + off);
                bL[2*p][0] = r[0]; bL[2*p][1] = r[1];
                bL[2*p+1][0] = r[2]; bL[2*p+1][1] = r[3];
            }
            #pragma unroll
            for (int mf = 0; mf < 4; mf++) {
                uint32_t aH[4], aL[4];
                uint32_t off = (uint32_t)((wm * 64 + mf * 16 + a_row) * (LDBE * 2)
                                          + (kk + a_col) * 2);
                ldmx4(aH, sAh + off);
                ldmx4(aL, sAl + off);
                #pragma unroll
                for (int nf = 0; nf < 8; nf++) {
                    mma16816(acc[mf][nf], aH, bH[nf]);
                    mma16816(acc[mf][nf], aH, bL[nf]);
                    mma16816(acc[mf][nf], aL, bH[nf]);
                }
            }
        }
        __syncthreads();
    }

    // ---- epilogue: per j-chunk score = sum_rows( max over its 128 cols ) ----
    float* smax = (float*)(sm + S_SMAX);   // [wn][row 0..127]
    #pragma unroll
    for (int mf = 0; mf < 4; mf++)
        #pragma unroll
        for (int h = 0; h < 2; h++) {
            float v = -3.402823466e38f;
            #pragma unroll
            for (int nf = 0; nf < 8; nf++) {
                v = fmaxf(v, acc[mf][nf][2*h]);
                v = fmaxf(v, acc[mf][nf][2*h + 1]);
            }
            v = fmaxf(v, __shfl_xor_sync(0xffffffffu, v, 1));
            v = fmaxf(v, __shfl_xor_sync(0xffffffffu, v, 2));
            if ((lane & 3) == 0)
                smax[wn * 128 + wm * 64 + mf * 16 + h * 8 + (lane >> 2)] = v;
        }
    __syncthreads();

    float* part = (float*)(sm + S_PART);   // [0..3]=j0, [4..7]=j1
    if (tid < 128) {
        float vj0 = fmaxf(smax[tid],       smax[128 + tid]);
        float vj1 = fmaxf(smax[256 + tid], smax[384 + tid]);
        #pragma unroll
        for (int off = 16; off; off >>= 1) {
            vj0 += __shfl_xor_sync(0xffffffffu, vj0, off);
            vj1 += __shfl_xor_sync(0xffffffffu, vj1, off);
        }
        if (lane == 0) { part[wid] = vj0; part[4 + wid] = vj1; }
    }
    __syncthreads();
    if (tid == 0) {
        g_scores[((size_t)b * NN + i) * NN + j0] = part[0] + part[1] + part[2] + part[3];
        if (have1)
            g_scores[((size_t)b * NN + i) * NN + j1] = part[4] + part[5] + part[6] + part[7];
    }
}

// ---------------------------------------------------------------------------
// Kernel C: top-7, weights, slot arrangement.  One warp per (b, i).
// ---------------------------------------------------------------------------
__global__ void topk_kernel() {
    int bi = blockIdx.x;
    int b = bi / NN, i = bi % NN;
    int lane = threadIdx.x;

    const float* srow = g_scores + ((size_t)b * NN + i) * NN;
    int j0 = lane, j1 = lane + 32;
    float v0 = (j0 < i) ? srow[j0] : -1e9f;
    float v1 = (j1 < i) ? srow[j1] : -1e9f;

    float vals[NSEL]; int idx[NSEL];
    for (int s = 0; s < NSEL; s++) {
        float bv; int bidx;
        if (v0 >= v1) { bv = v0; bidx = j0; } else { bv = v1; bidx = j1; }
        #pragma unroll
        for (int off = 16; off; off >>= 1) {
            float ov = __shfl_xor_sync(0xffffffffu, bv, off);
            int   oi = __shfl_xor_sync(0xffffffffu, bidx, off);
            if (ov > bv || (ov == bv && oi < bidx)) { bv = ov; bidx = oi; }
        }
        vals[s] = bv; idx[s] = bidx;
        if (j0 == bidx) v0 = -3.402823466e38f;
        if (j1 == bidx) v1 = -3.402823466e38f;
    }

    if (lane == 0) {
        int num_sel = (i < NSEL) ? i : NSEL;
        int vs = num_sel - 1;
        if (vs < 0) vs = 0;
        float vmin = vals[vs];
        float w[NSEL];
        for (int s = 0; s < NSEL; s++)
            w[s] = (s < num_sel) ? vals[s] / (vmin + EPSF) : 0.0f;
        int shift = NSEL - i; if (shift < 0) shift = 0;
        for (int t = 0; t < NSEL; t++) {
            int dst = ((size_t)b * NN + i) * NSEL + t;
            if (t >= shift) {
                g_selidx[dst] = idx[t - shift];
                g_selw[dst]   = w[t - shift];
            } else {
                g_selidx[dst] = 0;
                g_selw[dst]   = 0.0f;
            }
        }
    }
}

// ---------------------------------------------------------------------------
// Kernel D: out[b,n] = down_proj @ ext + chunk, via mma.sync bf16 hi/lo.
// CTA = (n, b).  M=128 (c), N=256 (full E), K=1024 (l).
// 8 warps in 2(M) x 4(N); each warp computes 64x64 of C.
// ---------------------------------------------------------------------------
__global__ __launch_bounds__(256) void out_kernel_mma(const float* __restrict__ x,
                                                      const float* __restrict__ dp,
                                                      float* __restrict__ out) {
    int n = blockIdx.x, b = blockIdx.y;

    extern __shared__ char sm[];
    uint32_t smb = smem_u32(sm);
    __shared__ int   s_idx[8];
    __shared__ float s_w[8];

    int tid = threadIdx.x, lane = tid & 31, wid = tid >> 5;
    int wm = wid & 1, wn = wid >> 1;

    if (tid < NSEL) {
        s_idx[tid] = g_selidx[((size_t)b * NN + n) * NSEL + tid];
        s_w[tid]   = g_selw[((size_t)b * NN + n) * NSEL + tid];
    }
    if (tid == NSEL) { s_idx[NSEL] = n; s_w[NSEL] = 1.0f; }
    __syncthreads();

    const __nv_bfloat16* xhb = g_xhi + (size_t)b * TT * EE;
    const __nv_bfloat16* xlb = g_xlo + (size_t)b * TT * EE;

    // per-thread A staging geometry: 4 float4s (rows of dp)
    int arow[4], acol4[4];
    #pragma unroll
    for (int r = 0; r < 4; r++) {
        int idx = tid + r * 256;
        arow[r]  = idx >> 3;
        acol4[r] = idx & 7;
    }

    auto issue_B = [&](int stage, int kt) {
        uint32_t base = smb + stage * O_STG;
        int l0 = kt * 32;
        int slot = l0 >> 7;
        int base_row = s_idx[slot] * CSZ + (l0 & 127);
        // 2 tiles x 32 rows x 32 segs = 2048 chunks
        #pragma unroll
        for (int t = 0; t < 8; t++) {
            int c = tid + t * 256;
            int tile = c >> 10;             // 0 = hi, 1 = lo
            int within = c & 1023;
            int row = within >> 5;          // 0..31
            int seg = within & 31;          // 16B segment (512B/row)
            const __nv_bfloat16* src = (tile ? xlb : xhb)
                + (size_t)(base_row + row) * EE + seg * 8;
            cp16(base + (tile ? O_BL : O_BH) + row * OLDE2 + seg * 16, src);
        }
    };

    auto store_A = [&](int stage, float4* av, float w) {
        uint32_t offh = stage * O_STG + O_AH;
        uint32_t offl = stage * O_STG + O_AL;
        #pragma unroll
        for (int r = 0; r < 4; r++) {
            float f[4] = {av[r].x * w, av[r].y * w, av[r].z * w, av[r].w * w};
            unsigned short h[4], l[4];
            #pragma unroll
            for (int q = 0; q < 4; q++) split_bf16(f[q], h[q], l[q]);
            uint32_t off = (uint32_t)(arow[r] * (LDBE * 2) + acol4[r] * 8);
            *(uint2*)(sm + offh + off) = make_uint2(pack2(h[0],h[1]), pack2(h[2],h[3]));
            *(uint2*)(sm + offl + off) = make_uint2(pack2(l[0],l[1]), pack2(l[2],l[3]));
        }
    };
    auto fetch_A = [&](float4* av, int kt) {
        int l0 = kt * 32;
        #pragma unroll
        for (int r = 0; r < 4; r++)
            av[r] = *(const float4*)(dp + (size_t)arow[r] * LEXT + l0 + acol4[r] * 4);
    };

    float acc[4][8][4];
    #pragma unroll
    for (int mf = 0; mf < 4; mf++)
        #pragma unroll
        for (int nf = 0; nf < 8; nf++)
            #pragma unroll
            for (int q = 0; q < 4; q++) acc[mf][nf][q] = 0.0f;

    int g8  = lane & 7, sel = lane >> 3;
    int a_row = g8 + ((sel & 1) ? 8 : 0);
    int a_col = (sel & 2) ? 8 : 0;
    int bk_off = g8 + ((sel & 1) ? 8 : 0);   // k offset within chunk (trans)
    int bn_off = (sel & 2) ? 8 : 0;          // n offset

    // prologue: stage kt=0
    {
        float4 av[4];
        fetch_A(av, 0);
        issue_B(0, 0);
        cp_commit();
        store_A(0, av, s_w[0]);
        cp_wait<0>();
        __syncthreads();
    }

    for (int kt = 0; kt < 32; kt++) {
        int buf = kt & 1;
        float4 av[4];
        if (kt < 31) {
            fetch_A(av, kt + 1);
            issue_B(buf ^ 1, kt + 1);
            cp_commit();
        }

        uint32_t sAh = smb + buf * O_STG + O_AH;
        uint32_t sAl = smb + buf * O_STG + O_AL;
        uint32_t sBh = smb + buf * O_STG + O_BH;
        uint32_t sBl = smb + buf * O_STG + O_BL;

        #pragma unroll
        for (int kk = 0; kk < 32; kk += 16) {
            uint32_t bH[8][2], bL[8][2];
            #pragma unroll
            for (int p = 0; p < 4; p++) {
                uint32_t off = (uint32_t)((kk + bk_off) * OLDE2
                                          + (wn * 64 + p * 16 + bn_off) * 2);
                uint32_t r[4];
                ldmx4t(r, sBh + off);
                bH[2*p][0] = r[0]; bH[2*p][1] = r[1];
                bH[2*p+1][0] = r[2]; bH[2*p+1][1] = r[3];
                ldmx4t(r, sBl + off);
                bL[2*p][0] = r[0]; bL[2*p][1] = r[1];
                bL[2*p+1][0] = r[2]; bL[2*p+1][1] = r[3];
            }
            #pragma unroll
            for (int mf = 0; mf < 4; mf++) {
                uint32_t aH[4], aL[4];
                uint32_t off = (uint32_t)((wm * 64 + mf * 16 + a_row) * (LDBE * 2)
                                          + (kk + a_col) * 2);
                ldmx4(aH, sAh + off);
                ldmx4(aL, sAl + off);
                #pragma unroll
                for (int nf = 0; nf < 8; nf++) {
                    mma16816(acc[mf][nf], aH, bH[nf]);
                    mma16816(acc[mf][nf], aH, bL[nf]);
                    mma16816(acc[mf][nf], aL, bH[nf]);
                }
            }
        }

        if (kt < 31) store_A(buf ^ 1, av, s_w[(kt + 1) >> 2]);
        cp_wait<0>();
        __syncthreads();
    }

    // epilogue: add residual (chunk n) and store
    const float* xb = x + (size_t)b * TT * EE;
    #pragma unroll
    for (int mf = 0; mf < 4; mf++)
        #pragma unroll
        for (int h = 0; h < 2; h++) {
            int row = wm * 64 + mf * 16 + h * 8 + (lane >> 2);
            const float* resrow = xb + ((size_t)n * CSZ + row) * EE;
            float* orow = out + ((size_t)b * TT + (size_t)n * CSZ + row) * EE;
            #pragma unroll
            for (int nf = 0; nf < 8; nf++) {
                int col = wn * 64 + nf * 8 + (lane & 3) * 2;
                float2 res = *(const float2*)(resrow + col);
                float2 o;
                o.x = acc[mf][nf][2*h]     + res.x;
                o.y = acc[mf][nf][2*h + 1] + res.y;
                *(float2*)(orow + col) = o;
            }
        }
}

// ---------------------------------------------------------------------------
extern "C" void kernel_launch(void* const* d_in, const int* in_sizes, int n_in,
                              void* d_out, int out_size) {
    const float* x  = (const float*)d_in[0];
    const float* dp = (const float*)d_in[1];
    if (in_sizes[0] == CSZ * LEXT) {  // down_proj came first
        dp = (const float*)d_in[0];
        x  = (const float*)d_in[1];
    }
    float* out = (float*)d_out;

    cudaFuncSetAttribute(score_kernel,
                         cudaFuncAttributeMaxDynamicSharedMemorySize, SCORE_SMEM);
    cudaFuncSetAttribute(out_kernel_mma,
                         cudaFuncAttributeMaxDynamicSharedMemorySize, OUT_SMEM);

    normalize_kernel<<<(BB * TT) / 8, 256>>>(x);
    score_kernel<<<dim3(1024, BB), 256, SCORE_SMEM>>>();
    topk_kernel<<<BB * NN, 32>>>();
    out_kernel_mma<<<dim3(NN, BB), 256, OUT_SMEM>>>(x, dp, out);
}

// round 13
// speedup vs baseline: 1.0255x; 1.0255x over previous
#include <cuda_runtime.h>
#include <cuda_bf16.h>
#include <math.h>
#include <stdint.h>

// Problem constants (fixed by reference)
#define BB      2
#define TT      8192
#define EE      256
#define CSZ     128
#define NN      64        // TT / CSZ
#define NSEL    7         // K - 1
#define LEXT    1024      // K * CS
#define EPSF    1e-6f
#define NPAIR   (NN * (NN - 1) / 2)   // 2016 causal pairs

// score kernel smem geometry
#define LDB     40                    // bf16 row stride of staged [rows][k] tiles
#define TILE_B  (128 * LDB * 2)       // 10240 bytes per tile
#define STG     (4 * TILE_B)          // 40960 bytes per stage (Ah,Al,Bh,Bl)
#define OFF_MAX (2 * STG)             // 81920: float smax[4][128]
#define OFF_PART (OFF_MAX + 4 * 128 * 4)
#define SCORE_SMEM (OFF_PART + 64)

// out kernel smem geometry
#define LDE      136                  // bf16 row stride of [k=32][e=128] B tiles
#define OA_TILE  (128 * LDB * 2)      // 10240: A tile (128 c x 32 l)
#define OB_TILE  (32 * LDE * 2)       // 8704:  B tile (32 l x 128 e)
#define OSTG     (2 * OA_TILE + 2 * OB_TILE)   // 37888 per stage
#define OUT_SMEM (2 * OSTG + 64)

// ---------------------------------------------------------------------------
// Scratch (static device globals — no allocation)
// ---------------------------------------------------------------------------
__device__ __nv_bfloat16 g_hi[(size_t)BB * TT * EE];   // bf16(cn), 8 MB
__device__ __nv_bfloat16 g_lo[(size_t)BB * TT * EE];   // bf16(cn - hi), 8 MB
__device__ __nv_bfloat16 g_xhi[(size_t)BB * TT * EE];  // bf16(x), 8 MB
__device__ __nv_bfloat16 g_xlo[(size_t)BB * TT * EE];  // bf16(x - xhi), 8 MB
__device__ float g_scores[BB * NN * NN];
__device__ int   g_selidx[BB * NN * NSEL];
__device__ float g_selw[BB * NN * NSEL];

// ---------------------------------------------------------------------------
// Base-PTX helpers (no 'a'-target instructions!)
// ---------------------------------------------------------------------------
__device__ __forceinline__ uint32_t smem_u32(const void* p) {
    uint32_t a;
    asm("{ .reg .u64 t; cvta.to.shared.u64 t, %1; cvt.u32.u64 %0, t; }"
        : "=r"(a) : "l"(p));
    return a;
}
__device__ __forceinline__ void cp16(uint32_t dst, const void* src) {
    asm volatile("cp.async.cg.shared.global [%0], [%1], 16;" :: "r"(dst), "l"(src));
}
__device__ __forceinline__ void cp_commit() {
    asm volatile("cp.async.commit_group;" ::: "memory");
}
template<int N> __device__ __forceinline__ void cp_wait() {
    asm volatile("cp.async.wait_group %0;" :: "n"(N) : "memory");
}
__device__ __forceinline__ void ldmx4(uint32_t* r, uint32_t addr) {
    asm volatile("ldmatrix.sync.aligned.m8n8.x4.shared.b16 {%0,%1,%2,%3}, [%4];"
                 : "=r"(r[0]), "=r"(r[1]), "=r"(r[2]), "=r"(r[3]) : "r"(addr));
}
__device__ __forceinline__ void ldmx4t(uint32_t* r, uint32_t addr) {
    asm volatile("ldmatrix.sync.aligned.m8n8.x4.trans.shared.b16 {%0,%1,%2,%3}, [%4];"
                 : "=r"(r[0]), "=r"(r[1]), "=r"(r[2]), "=r"(r[3]) : "r"(addr));
}
__device__ __forceinline__ void mma16816(float* c, const uint32_t* a, const uint32_t* b) {
    asm volatile("mma.sync.aligned.m16n8k16.row.col.f32.bf16.bf16.f32 "
                 "{%0,%1,%2,%3}, {%4,%5,%6,%7}, {%8,%9}, {%0,%1,%2,%3};"
                 : "+f"(c[0]), "+f"(c[1]), "+f"(c[2]), "+f"(c[3])
                 : "r"(a[0]), "r"(a[1]), "r"(a[2]), "r"(a[3]),
                   "r"(b[0]), "r"(b[1]));
}
__device__ __forceinline__ uint32_t pack2(unsigned short a, unsigned short b) {
    return (uint32_t)a | ((uint32_t)b << 16);
}
__device__ __forceinline__ void split_bf16(float f, unsigned short& h, unsigned short& l) {
    __nv_bfloat16 hb = __float2bfloat16(f);
    __nv_bfloat16 lb = __float2bfloat16(f - __bfloat162float(hb));
    h = *reinterpret_cast<unsigned short*>(&hb);
    l = *reinterpret_cast<unsigned short*>(&lb);
}

// ---------------------------------------------------------------------------
// Kernel A: row-normalize + hi/lo bf16 split of cn AND raw x.  One warp/row.
// ---------------------------------------------------------------------------
__global__ __launch_bounds__(256) void normalize_kernel(const float* __restrict__ x) {
    int row  = blockIdx.x * 8 + (threadIdx.x >> 5);
    int lane = threadIdx.x & 31;
    const float4* xr = (const float4*)(x + (size_t)row * EE);
    float4 v0 = xr[lane];
    float4 v1 = xr[lane + 32];
    float ss = v0.x*v0.x + v0.y*v0.y + v0.z*v0.z + v0.w*v0.w
             + v1.x*v1.x + v1.y*v1.y + v1.z*v1.z + v1.w*v1.w;
    #pragma unroll
    for (int off = 16; off; off >>= 1)
        ss += __shfl_xor_sync(0xffffffffu, ss, off);
    float inv = 1.0f / (sqrtf(ss) + EPSF);

    #pragma unroll
    for (int g = 0; g < 2; g++) {
        float4 v = g ? v1 : v0;
        float fr[4] = {v.x, v.y, v.z, v.w};
        unsigned short h[4], l[4], xh[4], xl[4];
        #pragma unroll
        for (int q = 0; q < 4; q++) {
            split_bf16(fr[q] * inv, h[q], l[q]);
            split_bf16(fr[q], xh[q], xl[q]);
        }
        size_t e = (size_t)row * EE + ((size_t)lane + (g ? 32 : 0)) * 4;
        *(uint2*)(g_hi  + e) = make_uint2(pack2(h[0],h[1]),  pack2(h[2],h[3]));
        *(uint2*)(g_lo  + e) = make_uint2(pack2(l[0],l[1]),  pack2(l[2],l[3]));
        *(uint2*)(g_xhi + e) = make_uint2(pack2(xh[0],xh[1]), pack2(xh[2],xh[3]));
        *(uint2*)(g_xlo + e) = make_uint2(pack2(xl[0],xl[1]), pack2(xl[2],xl[3]));
    }
}

// ---------------------------------------------------------------------------
// Kernel B: pair scores via mma.sync bf16 hi/lo (3-product fp32 emulation).
// Triangular grid: blockIdx.x = pair index t -> (i, j), j < i.
// 8 warps in 2(M) x 4(N); each warp computes 64x32 of C.
// Register-pipelined fragments: prefetch next-mf A / next-kk B during mmas.
// ---------------------------------------------------------------------------
__global__ void __launch_bounds__(256) score_kernel() {
    int t = blockIdx.x, b = blockIdx.y;
    int i = (int)((1.0f + sqrtf(1.0f + 8.0f * (float)t)) * 0.5f);
    while (i * (i - 1) / 2 > t) i--;
    while ((i + 1) * i / 2 <= t) i++;
    int j = t - i * (i - 1) / 2;

    extern __shared__ char sm[];
    uint32_t smb = smem_u32(sm);
    int tid = threadIdx.x, lane = tid & 31, wid = tid >> 5;
    int wm = wid & 1, wn = wid >> 1;

    const __nv_bfloat16* srcs[4];
    srcs[0] = g_hi + ((size_t)b * TT + (size_t)i * CSZ) * EE;   // Ah
    srcs[1] = g_lo + ((size_t)b * TT + (size_t)i * CSZ) * EE;   // Al
    srcs[2] = g_hi + ((size_t)b * TT + (size_t)j * CSZ) * EE;   // Bh
    srcs[3] = g_lo + ((size_t)b * TT + (size_t)j * CSZ) * EE;   // Bl

    float acc[4][4][4];
    #pragma unroll
    for (int mf = 0; mf < 4; mf++)
        #pragma unroll
        for (int nf = 0; nf < 4; nf++)
            #pragma unroll
            for (int q = 0; q < 4; q++) acc[mf][nf][q] = 0.0f;

    int g8  = lane & 7, sel = lane >> 3;
    int a_row = g8 + ((sel & 1) ? 8 : 0);
    int a_col = (sel & 2) ? 8 : 0;
    int b_row = g8 + ((sel >= 2) ? 8 : 0);
    int b_col = (sel & 1) ? 8 : 0;

    auto issue_stage = [&](int stage, int kt) {
        uint32_t sbase = smb + stage * STG;
        int k0 = kt * 32;
        #pragma unroll
        for (int tt = 0; tt < 8; tt++) {
            int chunk = tid + tt * 256;
            int tile  = chunk >> 9;
            int within = chunk & 511;
            int row = within >> 2;
            int seg = within & 3;
            cp16(sbase + tile * TILE_B + row * (LDB * 2) + seg * 16,
                 srcs[tile] + (size_t)row * EE + k0 + seg * 8);
        }
    };

    issue_stage(0, 0);
    cp_commit();

    for (int kt = 0; kt < 8; kt++) {
        int buf = kt & 1;
        if (kt < 7) {
            issue_stage(buf ^ 1, kt + 1);
            cp_commit();
            cp_wait<1>();
        } else {
            cp_wait<0>();
        }
        __syncthreads();

        uint32_t bAh = smb + buf * STG;
        uint32_t bAl = bAh + TILE_B;
        uint32_t bBh = bAh + 2 * TILE_B;
        uint32_t bBl = bAh + 3 * TILE_B;

        // fragment loaders
        auto load_B = [&](uint32_t (*bH)[2], uint32_t (*bL)[2], int kk) {
            #pragma unroll
            for (int p = 0; p < 2; p++) {
                uint32_t off = (uint32_t)((wn * 32 + p * 16 + b_row) * (LDB * 2)
                                          + (kk + b_col) * 2);
                uint32_t r[4];
                ldmx4(r, bBh + off);
                bH[2*p][0] = r[0]; bH[2*p][1] = r[1];
                bH[2*p+1][0] = r[2]; bH[2*p+1][1] = r[3];
                ldmx4(r, bBl + off);
                bL[2*p][0] = r[0]; bL[2*p][1] = r[1];
                bL[2*p+1][0] = r[2]; bL[2*p+1][1] = r[3];
            }
        };
        auto load_A = [&](uint32_t* aH, uint32_t* aL, int mf, int kk) {
            uint32_t off = (uint32_t)((wm * 64 + mf * 16 + a_row) * (LDB * 2)
                                      + (kk + a_col) * 2);
            ldmx4(aH, bAh + off);
            ldmx4(aL, bAl + off);
        };

        uint32_t bHc[4][2], bLc[4][2], aHc[4], aLc[4];
        uint32_t bHn[4][2], bLn[4][2], aHn[4], aLn[4];
        load_B(bHc, bLc, 0);
        load_A(aHc, aLc, 0, 0);

        #pragma unroll
        for (int kk = 0; kk < 32; kk += 16) {
            #pragma unroll
            for (int mf = 0; mf < 4; mf++) {
                // prefetch while mmas below issue
                if (mf < 3) {
                    load_A(aHn, aLn, mf + 1, kk);
                } else if (kk == 0) {
                    load_B(bHn, bLn, 16);
                    load_A(aHn, aLn, 0, 16);
                }
                #pragma unroll
                for (int nf = 0; nf < 4; nf++) {
                    mma16816(acc[mf][nf], aHc, bHc[nf]);
                    mma16816(acc[mf][nf], aHc, bLc[nf]);
                    mma16816(acc[mf][nf], aLc, bHc[nf]);
                }
                // rotate fragments
                #pragma unroll
                for (int q = 0; q < 4; q++) { aHc[q] = aHn[q]; aLc[q] = aLn[q]; }
                if (mf == 3 && kk == 0) {
                    #pragma unroll
                    for (int nf = 0; nf < 4; nf++) {
                        bHc[nf][0] = bHn[nf][0]; bHc[nf][1] = bHn[nf][1];
                        bLc[nf][0] = bLn[nf][0]; bLc[nf][1] = bLn[nf][1];
                    }
                }
            }
        }
        __syncthreads();
    }

    // ---- epilogue: score = sum_rows( max_cols C ) ----
    float* smax = (float*)(sm + OFF_MAX);
    #pragma unroll
    for (int mf = 0; mf < 4; mf++)
        #pragma unroll
        for (int h = 0; h < 2; h++) {
            float v = -3.402823466e38f;
            #pragma unroll
            for (int nf = 0; nf < 4; nf++) {
                v = fmaxf(v, acc[mf][nf][2*h]);
                v = fmaxf(v, acc[mf][nf][2*h + 1]);
            }
            v = fmaxf(v, __shfl_xor_sync(0xffffffffu, v, 1));
            v = fmaxf(v, __shfl_xor_sync(0xffffffffu, v, 2));
            if ((lane & 3) == 0)
                smax[wn * 128 + wm * 64 + mf * 16 + h * 8 + (lane >> 2)] = v;
        }
    __syncthreads();

    if (tid < 128) {
        float v = smax[tid];
        v = fmaxf(v, smax[128 + tid]);
        v = fmaxf(v, smax[256 + tid]);
        v = fmaxf(v, smax[384 + tid]);
        float ssum = v;
        #pragma unroll
        for (int off = 16; off; off >>= 1)
            ssum += __shfl_xor_sync(0xffffffffu, ssum, off);
        float* part = (float*)(sm + OFF_PART);
        if (lane == 0) part[wid] = ssum;
    }
    __syncthreads();
    if (tid == 0) {
        float* part = (float*)(sm + OFF_PART);
        g_scores[((size_t)b * NN + i) * NN + j] = part[0] + part[1] + part[2] + part[3];
    }
}

// ---------------------------------------------------------------------------
// Kernel C: top-7, weights, slot arrangement.  One warp per (b, i).
// ---------------------------------------------------------------------------
__global__ void topk_kernel() {
    int bi = blockIdx.x;
    int b = bi / NN, i = bi % NN;
    int lane = threadIdx.x;

    const float* srow = g_scores + ((size_t)b * NN + i) * NN;
    int j0 = lane, j1 = lane + 32;
    float v0 = (j0 < i) ? srow[j0] : -1e9f;
    float v1 = (j1 < i) ? srow[j1] : -1e9f;

    float vals[NSEL]; int idx[NSEL];
    for (int s = 0; s < NSEL; s++) {
        float bv; int bidx;
        if (v0 >= v1) { bv = v0; bidx = j0; } else { bv = v1; bidx = j1; }
        #pragma unroll
        for (int off = 16; off; off >>= 1) {
            float ov = __shfl_xor_sync(0xffffffffu, bv, off);
            int   oi = __shfl_xor_sync(0xffffffffu, bidx, off);
            if (ov > bv || (ov == bv && oi < bidx)) { bv = ov; bidx = oi; }
        }
        vals[s] = bv; idx[s] = bidx;
        if (j0 == bidx) v0 = -3.402823466e38f;
        if (j1 == bidx) v1 = -3.402823466e38f;
    }

    if (lane == 0) {
        int num_sel = (i < NSEL) ? i : NSEL;
        int vs = num_sel - 1;
        if (vs < 0) vs = 0;
        float vmin = vals[vs];
        float w[NSEL];
        for (int s = 0; s < NSEL; s++)
            w[s] = (s < num_sel) ? vals[s] / (vmin + EPSF) : 0.0f;
        int shift = NSEL - i; if (shift < 0) shift = 0;
        for (int t = 0; t < NSEL; t++) {
            int dst = ((size_t)b * NN + i) * NSEL + t;
            if (t >= shift) {
                g_selidx[dst] = idx[t - shift];
                g_selw[dst]   = w[t - shift];
            } else {
                g_selidx[dst] = 0;
                g_selw[dst]   = 0.0f;
            }
        }
    }
}

// ---------------------------------------------------------------------------
// Kernel D: out[b,n] = down_proj @ ext + chunk, via mma.sync bf16 hi/lo.
// CTA = (eh, n, b).  M=128 (c), N=128 (e-half), K=1024 (l).
// 8 warps in 2(M) x 4(N); each warp computes 64x32 of C.
// Register-pipelined fragments like score_kernel.
// ---------------------------------------------------------------------------
__global__ void __launch_bounds__(256) out_kernel_mma(const float* __restrict__ x,
                                                      const float* __restrict__ dp,
                                                      float* __restrict__ out) {
    int eh = blockIdx.x, n = blockIdx.y, b = blockIdx.z;

    extern __shared__ char sm[];
    uint32_t smb = smem_u32(sm);
    __shared__ int   s_idx[8];
    __shared__ float s_w[8];

    int tid = threadIdx.x, lane = tid & 31, wid = tid >> 5;
    int wm = wid & 1, wn = wid >> 1;
    int e0 = eh * 128;

    if (tid < NSEL) {
        s_idx[tid] = g_selidx[((size_t)b * NN + n) * NSEL + tid];
        s_w[tid]   = g_selw[((size_t)b * NN + n) * NSEL + tid];
    }
    if (tid == NSEL) { s_idx[NSEL] = n; s_w[NSEL] = 1.0f; }
    __syncthreads();

    const __nv_bfloat16* xhb = g_xhi + (size_t)b * TT * EE;
    const __nv_bfloat16* xlb = g_xlo + (size_t)b * TT * EE;

    // per-thread A staging geometry: 4 float4s (rows of dp)
    int arow[4], acol4[4];
    #pragma unroll
    for (int r = 0; r < 4; r++) {
        int idx = tid + r * 256;
        arow[r]  = idx >> 3;
        acol4[r] = idx & 7;
    }

    auto issue_B = [&](int stage, int kt) {
        uint32_t base = smb + stage * OSTG + 2 * OA_TILE;
        int l0 = kt * 32;
        int slot = l0 >> 7;
        int base_row = s_idx[slot] * CSZ + (l0 & 127);
        #pragma unroll
        for (int t = 0; t < 4; t++) {
            int idx = tid + t * 256;        // 0..1023
            int tile = idx >> 9;            // 0 = hi, 1 = lo
            int within = idx & 511;
            int row = within >> 4;          // 0..31
            int seg = within & 15;          // 16B segment
            const __nv_bfloat16* src = (tile ? xlb : xhb)
                + (size_t)(base_row + row) * EE + e0 + seg * 8;
            cp16(base + tile * OB_TILE + row * (LDE * 2) + seg * 16, src);
        }
    };

    auto store_A = [&](int stage, float4* av, float w) {
        uint32_t offh = stage * OSTG;
        uint32_t offl = offh + OA_TILE;
        #pragma unroll
        for (int r = 0; r < 4; r++) {
            float f[4] = {av[r].x * w, av[r].y * w, av[r].z * w, av[r].w * w};
            unsigned short h[4], l[4];
            #pragma unroll
            for (int q = 0; q < 4; q++) split_bf16(f[q], h[q], l[q]);
            uint32_t off = (uint32_t)(arow[r] * (LDB * 2) + acol4[r] * 8);
            *(uint2*)(sm + offh + off) = make_uint2(pack2(h[0],h[1]), pack2(h[2],h[3]));
            *(uint2*)(sm + offl + off) = make_uint2(pack2(l[0],l[1]), pack2(l[2],l[3]));
        }
    };
    auto fetch_A = [&](float4* av, int kt) {
        int l0 = kt * 32;
        #pragma unroll
        for (int r = 0; r < 4; r++)
            av[r] = *(const float4*)(dp + (size_t)arow[r] * LEXT + l0 + acol4[r] * 4);
    };

    float acc[4][4][4];
    #pragma unroll
    for (int mf = 0; mf < 4; mf++)
        #pragma unroll
        for (int nf = 0; nf < 4; nf++)
            #pragma unroll
            for (int q = 0; q < 4; q++) acc[mf][nf][q] = 0.0f;

    int g8  = lane & 7, sel = lane >> 3;
    int a_row = g8 + ((sel & 1) ? 8 : 0);
    int a_col = (sel & 2) ? 8 : 0;
    int bk_off = g8 + ((sel & 1) ? 8 : 0);   // k offset within chunk (trans)
    int bn_off = (sel & 2) ? 8 : 0;          // n offset

    // prologue: stage kt=0
    {
        float4 av[4];
        fetch_A(av, 0);
        issue_B(0, 0);
        cp_commit();
        store_A(0, av, s_w[0]);
        cp_wait<0>();
        __syncthreads();
    }

    for (int kt = 0; kt < 32; kt++) {
        int buf = kt & 1;
        float4 av[4];
        if (kt < 31) {
            fetch_A(av, kt + 1);
            issue_B(buf ^ 1, kt + 1);
            cp_commit();
        }

        uint32_t bAh = smb + buf * OSTG;
        uint32_t bAl = bAh + OA_TILE;
        uint32_t bBh = bAh + 2 * OA_TILE;
        uint32_t bBl = bBh + OB_TILE;

        auto load_B = [&](uint32_t (*bH)[2], uint32_t (*bL)[2], int kk) {
            #pragma unroll
            for (int p = 0; p < 2; p++) {
                uint32_t off = (uint32_t)((kk + bk_off) * (LDE * 2)
                                          + (wn * 32 + p * 16 + bn_off) * 2);
                uint32_t r[4];
                ldmx4t(r, bBh + off);
                bH[2*p][0] = r[0]; bH[2*p][1] = r[1];
                bH[2*p+1][0] = r[2]; bH[2*p+1][1] = r[3];
                ldmx4t(r, bBl + off);
                bL[2*p][0] = r[0]; bL[2*p][1] = r[1];
                bL[2*p+1][0] = r[2]; bL[2*p+1][1] = r[3];
            }
        };
        auto load_A = [&](uint32_t* aH, uint32_t* aL, int mf, int kk) {
            uint32_t off = (uint32_t)((wm * 64 + mf * 16 + a_row) * (LDB * 2)
                                      + (kk + a_col) * 2);
            ldmx4(aH, bAh + off);
            ldmx4(aL, bAl + off);
        };

        uint32_t bHc[4][2], bLc[4][2], aHc[4], aLc[4];
        uint32_t bHn[4][2], bLn[4][2], aHn[4], aLn[4];
        load_B(bHc, bLc, 0);
        load_A(aHc, aLc, 0, 0);

        #pragma unroll
        for (int kk = 0; kk < 32; kk += 16) {
            #pragma unroll
            for (int mf = 0; mf < 4; mf++) {
                if (mf < 3) {
                    load_A(aHn, aLn, mf + 1, kk);
                } else if (kk == 0) {
                    load_B(bHn, bLn, 16);
                    load_A(aHn, aLn, 0, 16);
                }
                #pragma unroll
                for (int nf = 0; nf < 4; nf++) {
                    mma16816(acc[mf][nf], aHc, bHc[nf]);
                    mma16816(acc[mf][nf], aHc, bLc[nf]);
                    mma16816(acc[mf][nf], aLc, bHc[nf]);
                }
                #pragma unroll
                for (int q = 0; q < 4; q++) { aHc[q] = aHn[q]; aLc[q] = aLn[q]; }
                if (mf == 3 && kk == 0) {
                    #pragma unroll
                    for (int nf = 0; nf < 4; nf++) {
                        bHc[nf][0] = bHn[nf][0]; bHc[nf][1] = bHn[nf][1];
                        bLc[nf][0] = bLn[nf][0]; bLc[nf][1] = bLn[nf][1];
                    }
                }
            }
        }

        if (kt < 31) store_A(buf ^ 1, av, s_w[(kt + 1) >> 2]);
        cp_wait<0>();
        __syncthreads();
    }

    // epilogue: add residual (chunk n) and store
    const float* xb = x + (size_t)b * TT * EE;
    #pragma unroll
    for (int mf = 0; mf < 4; mf++)
        #pragma unroll
        for (int h = 0; h < 2; h++) {
            int row = wm * 64 + mf * 16 + h * 8 + (lane >> 2);
            const float* resrow = xb + ((size_t)n * CSZ + row) * EE + e0;
            float* orow = out + ((size_t)b * TT + (size_t)n * CSZ + row) * EE + e0;
            #pragma unroll
            for (int nf = 0; nf < 4; nf++) {
                int col = wn * 32 + nf * 8 + (lane & 3) * 2;
                float2 res = *(const float2*)(resrow + col);
                float2 o;
                o.x = acc[mf][nf][2*h]     + res.x;
                o.y = acc[mf][nf][2*h + 1] + res.y;
                *(float2*)(orow + col) = o;
            }
        }
}

// ---------------------------------------------------------------------------
extern "C" void kernel_launch(void* const* d_in, const int* in_sizes, int n_in,
                              void* d_out, int out_size) {
    const float* x  = (const float*)d_in[0];
    const float* dp = (const float*)d_in[1];
    if (in_sizes[0] == CSZ * LEXT) {  // down_proj came first
        dp = (const float*)d_in[0];
        x  = (const float*)d_in[1];
    }
    float* out = (float*)d_out;

    cudaFuncSetAttribute(score_kernel,
                         cudaFuncAttributeMaxDynamicSharedMemorySize, SCORE_SMEM);
    cudaFuncSetAttribute(out_kernel_mma,
                         cudaFuncAttributeMaxDynamicSharedMemorySize, OUT_SMEM);

    normalize_kernel<<<(BB * TT) / 8, 256>>>(x);
    score_kernel<<<dim3(NPAIR, BB), 256, SCORE_SMEM>>>();
    topk_kernel<<<BB * NN, 32>>>();
    out_kernel_mma<<<dim3(2, NN, BB), 256, OUT_SMEM>>>(x, dp, out);
}

// round 14
// speedup vs baseline: 1.0673x; 1.0407x over previous
#include <cuda_runtime.h>
#include <cuda_bf16.h>
#include <math.h>
#include <stdint.h>

// Problem constants (fixed by reference)
#define BB      2
#define TT      8192
#define EE      256
#define CSZ     128
#define NN      64        // TT / CSZ
#define NSEL    7         // K - 1
#define LEXT    1024      // K * CS
#define EPSF    1e-6f
#define NPAIR   (NN * (NN - 1) / 2)   // 2016 causal pairs

// score kernel smem geometry
#define LDB     40                    // bf16 row stride of staged [rows][k] tiles
#define TILE_B  (128 * LDB * 2)       // 10240 bytes per tile
#define STG     (4 * TILE_B)          // 40960 bytes per stage (Ah,Al,Bh,Bl)
#define OFF_MAX (2 * STG)             // 81920: float smax[4][128]
#define OFF_PART (OFF_MAX + 4 * 128 * 4)
#define SCORE_SMEM (OFF_PART + 64)

// out kernel smem geometry
#define LDE      136                  // bf16 row stride of [k=32][e=128] B tiles
#define OA_TILE  (128 * LDB * 2)      // 10240: A tile (128 c x 32 l)
#define OB_TILE  (32 * LDE * 2)       // 8704:  B tile (32 l x 128 e)
#define OSTG     (2 * OA_TILE + 2 * OB_TILE)   // 37888 per stage
#define OUT_SMEM (2 * OSTG + 64)

// ---------------------------------------------------------------------------
// Scratch (static device globals — no allocation)
// ---------------------------------------------------------------------------
__device__ __nv_bfloat16 g_hi[(size_t)BB * TT * EE];   // bf16(cn), 8 MB
__device__ __nv_bfloat16 g_lo[(size_t)BB * TT * EE];   // bf16(cn - hi), 8 MB
__device__ __nv_bfloat16 g_xhi[(size_t)BB * TT * EE];  // bf16(x), 8 MB
__device__ __nv_bfloat16 g_xlo[(size_t)BB * TT * EE];  // bf16(x - xhi), 8 MB
__device__ float g_scores[BB * NN * NN];
__device__ int   g_selidx[BB * NN * NSEL];
__device__ float g_selw[BB * NN * NSEL];

// ---------------------------------------------------------------------------
// Base-PTX helpers (no 'a'-target instructions!)
// ---------------------------------------------------------------------------
__device__ __forceinline__ uint32_t smem_u32(const void* p) {
    uint32_t a;
    asm("{ .reg .u64 t; cvta.to.shared.u64 t, %1; cvt.u32.u64 %0, t; }"
        : "=r"(a) : "l"(p));
    return a;
}
__device__ __forceinline__ void cp16(uint32_t dst, const void* src) {
    asm volatile("cp.async.cg.shared.global [%0], [%1], 16;" :: "r"(dst), "l"(src));
}
__device__ __forceinline__ void cp_commit() {
    asm volatile("cp.async.commit_group;" ::: "memory");
}
template<int N> __device__ __forceinline__ void cp_wait() {
    asm volatile("cp.async.wait_group %0;" :: "n"(N) : "memory");
}
__device__ __forceinline__ void ldmx4(uint32_t* r, uint32_t addr) {
    asm volatile("ldmatrix.sync.aligned.m8n8.x4.shared.b16 {%0,%1,%2,%3}, [%4];"
                 : "=r"(r[0]), "=r"(r[1]), "=r"(r[2]), "=r"(r[3]) : "r"(addr));
}
__device__ __forceinline__ void ldmx4t(uint32_t* r, uint32_t addr) {
    asm volatile("ldmatrix.sync.aligned.m8n8.x4.trans.shared.b16 {%0,%1,%2,%3}, [%4];"
                 : "=r"(r[0]), "=r"(r[1]), "=r"(r[2]), "=r"(r[3]) : "r"(addr));
}
__device__ __forceinline__ void mma16816(float* c, const uint32_t* a, const uint32_t* b) {
    asm volatile("mma.sync.aligned.m16n8k16.row.col.f32.bf16.bf16.f32 "
                 "{%0,%1,%2,%3}, {%4,%5,%6,%7}, {%8,%9}, {%0,%1,%2,%3};"
                 : "+f"(c[0]), "+f"(c[1]), "+f"(c[2]), "+f"(c[3])
                 : "r"(a[0]), "r"(a[1]), "r"(a[2]), "r"(a[3]),
                   "r"(b[0]), "r"(b[1]));
}
__device__ __forceinline__ uint32_t pack2(unsigned short a, unsigned short b) {
    return (uint32_t)a | ((uint32_t)b << 16);
}
__device__ __forceinline__ void split_bf16(float f, unsigned short& h, unsigned short& l) {
    __nv_bfloat16 hb = __float2bfloat16(f);
    __nv_bfloat16 lb = __float2bfloat16(f - __bfloat162float(hb));
    h = *reinterpret_cast<unsigned short*>(&hb);
    l = *reinterpret_cast<unsigned short*>(&lb);
}

// ---------------------------------------------------------------------------
// Kernel A: row-normalize + hi/lo bf16 split of cn AND raw x.  One warp/row.
// ---------------------------------------------------------------------------
__global__ __launch_bounds__(256) void normalize_kernel(const float* __restrict__ x) {
    int row  = blockIdx.x * 8 + (threadIdx.x >> 5);
    int lane = threadIdx.x & 31;
    const float4* xr = (const float4*)(x + (size_t)row * EE);
    float4 v0 = xr[lane];
    float4 v1 = xr[lane + 32];
    float ss = v0.x*v0.x + v0.y*v0.y + v0.z*v0.z + v0.w*v0.w
             + v1.x*v1.x + v1.y*v1.y + v1.z*v1.z + v1.w*v1.w;
    #pragma unroll
    for (int off = 16; off; off >>= 1)
        ss += __shfl_xor_sync(0xffffffffu, ss, off);
    float inv = 1.0f / (sqrtf(ss) + EPSF);

    #pragma unroll
    for (int g = 0; g < 2; g++) {
        float4 v = g ? v1 : v0;
        float fr[4] = {v.x, v.y, v.z, v.w};
        unsigned short h[4], l[4], xh[4], xl[4];
        #pragma unroll
        for (int q = 0; q < 4; q++) {
            split_bf16(fr[q] * inv, h[q], l[q]);
            split_bf16(fr[q], xh[q], xl[q]);
        }
        size_t e = (size_t)row * EE + ((size_t)lane + (g ? 32 : 0)) * 4;
        *(uint2*)(g_hi  + e) = make_uint2(pack2(h[0],h[1]),  pack2(h[2],h[3]));
        *(uint2*)(g_lo  + e) = make_uint2(pack2(l[0],l[1]),  pack2(l[2],l[3]));
        *(uint2*)(g_xhi + e) = make_uint2(pack2(xh[0],xh[1]), pack2(xh[2],xh[3]));
        *(uint2*)(g_xlo + e) = make_uint2(pack2(xl[0],xl[1]), pack2(xl[2],xl[3]));
    }
}

// ---------------------------------------------------------------------------
// Kernel B: pair scores via mma.sync bf16 hi/lo (3-product fp32 emulation).
// Triangular grid: blockIdx.x = pair index t -> (i, j), j < i.
// 8 warps in 2(M) x 4(N); each warp computes 64x32 of C.
// kk-phase stagger: half the warps (by SMSP pairing) process kk=16 first so
// their ldsm bursts overlap the other half's mma bursts (crossbar || tensor).
// ---------------------------------------------------------------------------
__global__ void __launch_bounds__(256, 2) score_kernel() {
    int t = blockIdx.x, b = blockIdx.y;
    int i = (int)((1.0f + sqrtf(1.0f + 8.0f * (float)t)) * 0.5f);
    while (i * (i - 1) / 2 > t) i--;
    while ((i + 1) * i / 2 <= t) i++;
    int j = t - i * (i - 1) / 2;

    extern __shared__ char sm[];
    uint32_t smb = smem_u32(sm);
    int tid = threadIdx.x, lane = tid & 31, wid = tid >> 5;
    int wm = wid & 1, wn = wid >> 1;
    int kkbase = ((wid >> 2) & 1) << 4;   // 0 or 16 — per-warp phase

    const __nv_bfloat16* srcs[4];
    srcs[0] = g_hi + ((size_t)b * TT + (size_t)i * CSZ) * EE;   // Ah
    srcs[1] = g_lo + ((size_t)b * TT + (size_t)i * CSZ) * EE;   // Al
    srcs[2] = g_hi + ((size_t)b * TT + (size_t)j * CSZ) * EE;   // Bh
    srcs[3] = g_lo + ((size_t)b * TT + (size_t)j * CSZ) * EE;   // Bl

    float acc[4][4][4];
    #pragma unroll
    for (int mf = 0; mf < 4; mf++)
        #pragma unroll
        for (int nf = 0; nf < 4; nf++)
            #pragma unroll
            for (int q = 0; q < 4; q++) acc[mf][nf][q] = 0.0f;

    int g8  = lane & 7, sel = lane >> 3;
    int a_row = g8 + ((sel & 1) ? 8 : 0);
    int a_col = (sel & 2) ? 8 : 0;
    int b_row = g8 + ((sel >= 2) ? 8 : 0);
    int b_col = (sel & 1) ? 8 : 0;

    auto issue_stage = [&](int stage, int kt) {
        uint32_t sbase = smb + stage * STG;
        int k0 = kt * 32;
        #pragma unroll
        for (int tt = 0; tt < 8; tt++) {
            int chunk = tid + tt * 256;
            int tile  = chunk >> 9;
            int within = chunk & 511;
            int row = within >> 2;
            int seg = within & 3;
            cp16(sbase + tile * TILE_B + row * (LDB * 2) + seg * 16,
                 srcs[tile] + (size_t)row * EE + k0 + seg * 8);
        }
    };

    issue_stage(0, 0);
    cp_commit();

    for (int kt = 0; kt < 8; kt++) {
        int buf = kt & 1;
        if (kt < 7) {
            issue_stage(buf ^ 1, kt + 1);
            cp_commit();
            cp_wait<1>();
        } else {
            cp_wait<0>();
        }
        __syncthreads();

        uint32_t bAh = smb + buf * STG;
        uint32_t bAl = bAh + TILE_B;
        uint32_t bBh = bAh + 2 * TILE_B;
        uint32_t bBl = bAh + 3 * TILE_B;

        #pragma unroll
        for (int kx = 0; kx < 2; kx++) {
            int kk = kkbase ^ (kx << 4);   // phase-staggered k-half order
            // B fragments once per kk (16 regs live)
            uint32_t bH[4][2], bL[4][2];
            #pragma unroll
            for (int p = 0; p < 2; p++) {
                uint32_t off = (uint32_t)((wn * 32 + p * 16 + b_row) * (LDB * 2)
                                          + (kk + b_col) * 2);
                uint32_t r[4];
                ldmx4(r, bBh + off);
                bH[2*p][0] = r[0]; bH[2*p][1] = r[1];
                bH[2*p+1][0] = r[2]; bH[2*p+1][1] = r[3];
                ldmx4(r, bBl + off);
                bL[2*p][0] = r[0]; bL[2*p][1] = r[1];
                bL[2*p+1][0] = r[2]; bL[2*p+1][1] = r[3];
            }
            // A fragments per-mf (8 regs live at a time)
            #pragma unroll
            for (int mf = 0; mf < 4; mf++) {
                uint32_t aH[4], aL[4];
                uint32_t off = (uint32_t)((wm * 64 + mf * 16 + a_row) * (LDB * 2)
                                          + (kk + a_col) * 2);
                ldmx4(aH, bAh + off);
                ldmx4(aL, bAl + off);
                #pragma unroll
                for (int nf = 0; nf < 4; nf++) {
                    mma16816(acc[mf][nf], aH, bH[nf]);
                    mma16816(acc[mf][nf], aH, bL[nf]);
                    mma16816(acc[mf][nf], aL, bH[nf]);
                }
            }
        }
        __syncthreads();
    }

    // ---- epilogue: score = sum_rows( max_cols C ) ----
    float* smax = (float*)(sm + OFF_MAX);
    #pragma unroll
    for (int mf = 0; mf < 4; mf++)
        #pragma unroll
        for (int h = 0; h < 2; h++) {
            float v = -3.402823466e38f;
            #pragma unroll
            for (int nf = 0; nf < 4; nf++) {
                v = fmaxf(v, acc[mf][nf][2*h]);
                v = fmaxf(v, acc[mf][nf][2*h + 1]);
            }
            v = fmaxf(v, __shfl_xor_sync(0xffffffffu, v, 1));
            v = fmaxf(v, __shfl_xor_sync(0xffffffffu, v, 2));
            if ((lane & 3) == 0)
                smax[wn * 128 + wm * 64 + mf * 16 + h * 8 + (lane >> 2)] = v;
        }
    __syncthreads();

    if (tid < 128) {
        float v = smax[tid];
        v = fmaxf(v, smax[128 + tid]);
        v = fmaxf(v, smax[256 + tid]);
        v = fmaxf(v, smax[384 + tid]);
        float ssum = v;
        #pragma unroll
        for (int off = 16; off; off >>= 1)
            ssum += __shfl_xor_sync(0xffffffffu, ssum, off);
        float* part = (float*)(sm + OFF_PART);
        if (lane == 0) part[wid] = ssum;
    }
    __syncthreads();
    if (tid == 0) {
        float* part = (float*)(sm + OFF_PART);
        g_scores[((size_t)b * NN + i) * NN + j] = part[0] + part[1] + part[2] + part[3];
    }
}

// ---------------------------------------------------------------------------
// Kernel C: top-7, weights, slot arrangement.  One warp per (b, i).
// ---------------------------------------------------------------------------
__global__ void topk_kernel() {
    int bi = blockIdx.x;
    int b = bi / NN, i = bi % NN;
    int lane = threadIdx.x;

    const float* srow = g_scores + ((size_t)b * NN + i) * NN;
    int j0 = lane, j1 = lane + 32;
    float v0 = (j0 < i) ? srow[j0] : -1e9f;
    float v1 = (j1 < i) ? srow[j1] : -1e9f;

    float vals[NSEL]; int idx[NSEL];
    for (int s = 0; s < NSEL; s++) {
        float bv; int bidx;
        if (v0 >= v1) { bv = v0; bidx = j0; } else { bv = v1; bidx = j1; }
        #pragma unroll
        for (int off = 16; off; off >>= 1) {
            float ov = __shfl_xor_sync(0xffffffffu, bv, off);
            int   oi = __shfl_xor_sync(0xffffffffu, bidx, off);
            if (ov > bv || (ov == bv && oi < bidx)) { bv = ov; bidx = oi; }
        }
        vals[s] = bv; idx[s] = bidx;
        if (j0 == bidx) v0 = -3.402823466e38f;
        if (j1 == bidx) v1 = -3.402823466e38f;
    }

    if (lane == 0) {
        int num_sel = (i < NSEL) ? i : NSEL;
        int vs = num_sel - 1;
        if (vs < 0) vs = 0;
        float vmin = vals[vs];
        float w[NSEL];
        for (int s = 0; s < NSEL; s++)
            w[s] = (s < num_sel) ? vals[s] / (vmin + EPSF) : 0.0f;
        int shift = NSEL - i; if (shift < 0) shift = 0;
        for (int t = 0; t < NSEL; t++) {
            int dst = ((size_t)b * NN + i) * NSEL + t;
            if (t >= shift) {
                g_selidx[dst] = idx[t - shift];
                g_selw[dst]   = w[t - shift];
            } else {
                g_selidx[dst] = 0;
                g_selw[dst]   = 0.0f;
            }
        }
    }
}

// ---------------------------------------------------------------------------
// Kernel D: out[b,n] = down_proj @ ext + chunk, via mma.sync bf16 hi/lo.
// CTA = (eh, n, b).  M=128 (c), N=128 (e-half), K=1024 (l).
// 8 warps in 2(M) x 4(N); each warp computes 64x32 of C.  kk-phase stagger.
// ---------------------------------------------------------------------------
__global__ void __launch_bounds__(256, 2) out_kernel_mma(const float* __restrict__ x,
                                                         const float* __restrict__ dp,
                                                         float* __restrict__ out) {
    int eh = blockIdx.x, n = blockIdx.y, b = blockIdx.z;

    extern __shared__ char sm[];
    uint32_t smb = smem_u32(sm);
    __shared__ int   s_idx[8];
    __shared__ float s_w[8];

    int tid = threadIdx.x, lane = tid & 31, wid = tid >> 5;
    int wm = wid & 1, wn = wid >> 1;
    int e0 = eh * 128;
    int kkbase = ((wid >> 2) & 1) << 4;   // 0 or 16 — per-warp phase

    if (tid < NSEL) {
        s_idx[tid] = g_selidx[((size_t)b * NN + n) * NSEL + tid];
        s_w[tid]   = g_selw[((size_t)b * NN + n) * NSEL + tid];
    }
    if (tid == NSEL) { s_idx[NSEL] = n; s_w[NSEL] = 1.0f; }
    __syncthreads();

    const __nv_bfloat16* xhb = g_xhi + (size_t)b * TT * EE;
    const __nv_bfloat16* xlb = g_xlo + (size_t)b * TT * EE;

    // per-thread A staging geometry: 4 float4s (rows of dp)
    int arow[4], acol4[4];
    #pragma unroll
    for (int r = 0; r < 4; r++) {
        int idx = tid + r * 256;
        arow[r]  = idx >> 3;
        acol4[r] = idx & 7;
    }

    auto issue_B = [&](int stage, int kt) {
        uint32_t base = smb + stage * OSTG + 2 * OA_TILE;
        int l0 = kt * 32;
        int slot = l0 >> 7;
        int base_row = s_idx[slot] * CSZ + (l0 & 127);
        #pragma unroll
        for (int t = 0; t < 4; t++) {
            int idx = tid + t * 256;        // 0..1023
            int tile = idx >> 9;            // 0 = hi, 1 = lo
            int within = idx & 511;
            int row = within >> 4;          // 0..31
            int seg = within & 15;          // 16B segment
            const __nv_bfloat16* src = (tile ? xlb : xhb)
                + (size_t)(base_row + row) * EE + e0 + seg * 8;
            cp16(base + tile * OB_TILE + row * (LDE * 2) + seg * 16, src);
        }
    };

    auto store_A = [&](int stage, float4* av, float w) {
        uint32_t offh = stage * OSTG;
        uint32_t offl = offh + OA_TILE;
        #pragma unroll
        for (int r = 0; r < 4; r++) {
            float f[4] = {av[r].x * w, av[r].y * w, av[r].z * w, av[r].w * w};
            unsigned short h[4], l[4];
            #pragma unroll
            for (int q = 0; q < 4; q++) split_bf16(f[q], h[q], l[q]);
            uint32_t off = (uint32_t)(arow[r] * (LDB * 2) + acol4[r] * 8);
            *(uint2*)(sm + offh + off) = make_uint2(pack2(h[0],h[1]), pack2(h[2],h[3]));
            *(uint2*)(sm + offl + off) = make_uint2(pack2(l[0],l[1]), pack2(l[2],l[3]));
        }
    };
    auto fetch_A = [&](float4* av, int kt) {
        int l0 = kt * 32;
        #pragma unroll
        for (int r = 0; r < 4; r++)
            av[r] = *(const float4*)(dp + (size_t)arow[r] * LEXT + l0 + acol4[r] * 4);
    };

    float acc[4][4][4];
    #pragma unroll
    for (int mf = 0; mf < 4; mf++)
        #pragma unroll
        for (int nf = 0; nf < 4; nf++)
            #pragma unroll
            for (int q = 0; q < 4; q++) acc[mf][nf][q] = 0.0f;

    int g8  = lane & 7, sel = lane >> 3;
    int a_row = g8 + ((sel & 1) ? 8 : 0);
    int a_col = (sel & 2) ? 8 : 0;
    int bk_off = g8 + ((sel & 1) ? 8 : 0);   // k offset within chunk (trans)
    int bn_off = (sel & 2) ? 8 : 0;          // n offset

    // prologue: stage kt=0
    {
        float4 av[4];
        fetch_A(av, 0);
        issue_B(0, 0);
        cp_commit();
        store_A(0, av, s_w[0]);
        cp_wait<0>();
        __syncthreads();
    }

    for (int kt = 0; kt < 32; kt++) {
        int buf = kt & 1;
        float4 av[4];
        if (kt < 31) {
            fetch_A(av, kt + 1);
            issue_B(buf ^ 1, kt + 1);
            cp_commit();
        }

        uint32_t bAh = smb + buf * OSTG;
        uint32_t bAl = bAh + OA_TILE;
        uint32_t bBh = bAh + 2 * OA_TILE;
        uint32_t bBl = bBh + OB_TILE;

        #pragma unroll
        for (int kx = 0; kx < 2; kx++) {
            int kk = kkbase ^ (kx << 4);   // phase-staggered k-half order
            uint32_t bH[4][2], bL[4][2];
            #pragma unroll
            for (int p = 0; p < 2; p++) {
                uint32_t off = (uint32_t)((kk + bk_off) * (LDE * 2)
                                          + (wn * 32 + p * 16 + bn_off) * 2);
                uint32_t r[4];
                ldmx4t(r, bBh + off);
                bH[2*p][0] = r[0]; bH[2*p][1] = r[1];
                bH[2*p+1][0] = r[2]; bH[2*p+1][1] = r[3];
                ldmx4t(r, bBl + off);
                bL[2*p][0] = r[0]; bL[2*p][1] = r[1];
                bL[2*p+1][0] = r[2]; bL[2*p+1][1] = r[3];
            }
            #pragma unroll
            for (int mf = 0; mf < 4; mf++) {
                uint32_t aH[4], aL[4];
                uint32_t off = (uint32_t)((wm * 64 + mf * 16 + a_row) * (LDB * 2)
                                          + (kk + a_col) * 2);
                ldmx4(aH, bAh + off);
                ldmx4(aL, bAl + off);
                #pragma unroll
                for (int nf = 0; nf < 4; nf++) {
                    mma16816(acc[mf][nf], aH, bH[nf]);
                    mma16816(acc[mf][nf], aH, bL[nf]);
                    mma16816(acc[mf][nf], aL, bH[nf]);
                }
            }
        }

        if (kt < 31) store_A(buf ^ 1, av, s_w[(kt + 1) >> 2]);
        cp_wait<0>();
        __syncthreads();
    }

    // epilogue: add residual (chunk n) and store
    const float* xb = x + (size_t)b * TT * EE;
    #pragma unroll
    for (int mf = 0; mf < 4; mf++)
        #pragma unroll
        for (int h = 0; h < 2; h++) {
            int row = wm * 64 + mf * 16 + h * 8 + (lane >> 2);
            const float* resrow = xb + ((size_t)n * CSZ + row) * EE + e0;
            float* orow = out + ((size_t)b * TT + (size_t)n * CSZ + row) * EE + e0;
            #pragma unroll
            for (int nf = 0; nf < 4; nf++) {
                int col = wn * 32 + nf * 8 + (lane & 3) * 2;
                float2 res = *(const float2*)(resrow + col);
                float2 o;
                o.x = acc[mf][nf][2*h]     + res.x;
                o.y = acc[mf][nf][2*h + 1] + res.y;
                *(float2*)(orow + col) = o;
            }
        }
}

// ---------------------------------------------------------------------------
extern "C" void kernel_launch(void* const* d_in, const int* in_sizes, int n_in,
                              void* d_out, int out_size) {
    const float* x  = (const float*)d_in[0];
    const float* dp = (const float*)d_in[1];
    if (in_sizes[0] == CSZ * LEXT) {  // down_proj came first
        dp = (const float*)d_in[0];
        x  = (const float*)d_in[1];
    }
    float* out = (float*)d_out;

    cudaFuncSetAttribute(score_kernel,
                         cudaFuncAttributeMaxDynamicSharedMemorySize, SCORE_SMEM);
    cudaFuncSetAttribute(out_kernel_mma,
                         cudaFuncAttributeMaxDynamicSharedMemorySize, OUT_SMEM);

    normalize_kernel<<<(BB * TT) / 8, 256>>>(x);
    score_kernel<<<dim3(NPAIR, BB), 256, SCORE_SMEM>>>();
    topk_kernel<<<BB * NN, 32>>>();
    out_kernel_mma<<<dim3(2, NN, BB), 256, OUT_SMEM>>>(x, dp, out);
}